// round 9
// baseline (speedup 1.0000x reference)
#include <cuda_runtime.h>
#include <cstdint>

// Problem constants (fixed by the reference setup)
#define BB   64
#define TT   1024
#define INC  16
#define NN   512
#define RR   16
#define OUTC 8
#define AA   0.1f   // DT / TAU

typedef unsigned long long u64;

// ---------------- packed f32x2 helpers (sm_103a dual-fp32 pipe) --------------
__device__ __forceinline__ u64 pk2(float lo, float hi) {
    u64 r; asm("mov.b64 %0, {%1, %2};" : "=l"(r) : "f"(lo), "f"(hi)); return r;
}
__device__ __forceinline__ void upk2(u64 v, float& lo, float& hi) {
    asm("mov.b64 {%0, %1}, %2;" : "=f"(lo), "=f"(hi) : "l"(v));
}
__device__ __forceinline__ u64 fma2(u64 a, u64 b, u64 c) {
    u64 d; asm("fma.rn.f32x2 %0, %1, %2, %3;" : "=l"(d) : "l"(a), "l"(b), "l"(c)); return d;
}
__device__ __forceinline__ u64 mul2(u64 a, u64 b) {
    u64 d; asm("mul.rn.f32x2 %0, %1, %2;" : "=l"(d) : "l"(a), "l"(b)); return d;
}
__device__ __forceinline__ u64 add2(u64 a, u64 b) {
    u64 d; asm("add.rn.f32x2 %0, %1, %2;" : "=l"(d) : "l"(a), "l"(b)); return d;
}

// Accurate-enough fast tanh: 1 - 2/(exp(2x)+1) via ex2.approx + rcp.approx.
__device__ __forceinline__ float fast_tanh(float x) {
    float e;
    asm("ex2.approx.f32 %0, %1;" : "=f"(e) : "f"(x * 2.885390082f)); // 2*log2(e)
    float r;
    asm("rcp.approx.f32 %0, %1;" : "=f"(r) : "f"(e + 1.0f));
    return fmaf(-2.0f, r, 1.0f);
}

// ---------------------------------------------------------------------------
// Kernel A: Inp[b,t,n] = sum_i X[b,t,i] * In_w[n,i], written into the hidden
// region of d_out (scratch aliasing with the scan). Tiled, In_w in registers.
// ---------------------------------------------------------------------------
#define IROWS 64
__global__ __launch_bounds__(256) void inp_kernel(const float* __restrict__ x,
                                                  const float* __restrict__ inw,
                                                  float* __restrict__ inp_out) {
    const int tid = threadIdx.x;
    const int r0  = blockIdx.x * IROWS;
    __shared__ float4 sx4[IROWS * INC / 4];

    sx4[tid] = reinterpret_cast<const float4*>(x)[(size_t)r0 * (INC / 4) + tid];

    const int n0 = tid * 2;
    float w0[INC], w1[INC];
    {
        const float4* a4 = reinterpret_cast<const float4*>(inw + (size_t)n0 * INC);
        const float4* b4 = reinterpret_cast<const float4*>(inw + (size_t)(n0 + 1) * INC);
#pragma unroll
        for (int i = 0; i < 4; i++) {
            float4 a = __ldg(&a4[i]);
            w0[4 * i + 0] = a.x; w0[4 * i + 1] = a.y; w0[4 * i + 2] = a.z; w0[4 * i + 3] = a.w;
            float4 c = __ldg(&b4[i]);
            w1[4 * i + 0] = c.x; w1[4 * i + 1] = c.y; w1[4 * i + 2] = c.z; w1[4 * i + 3] = c.w;
        }
    }
    __syncthreads();

    float2* out2 = reinterpret_cast<float2*>(inp_out) + (size_t)r0 * (NN / 2) + tid;

#pragma unroll 4
    for (int j = 0; j < IROWS; j++) {
        float acc0 = 0.0f, acc1 = 0.0f;
#pragma unroll
        for (int q = 0; q < 4; q++) {
            float4 xv = sx4[j * 4 + q];
            acc0 = fmaf(w0[4 * q + 0], xv.x, acc0);
            acc0 = fmaf(w0[4 * q + 1], xv.y, acc0);
            acc0 = fmaf(w0[4 * q + 2], xv.z, acc0);
            acc0 = fmaf(w0[4 * q + 3], xv.w, acc0);
            acc1 = fmaf(w1[4 * q + 0], xv.x, acc1);
            acc1 = fmaf(w1[4 * q + 1], xv.y, acc1);
            acc1 = fmaf(w1[4 * q + 2], xv.z, acc1);
            acc1 = fmaf(w1[4 * q + 3], xv.w, acc1);
        }
        out2[(size_t)j * (NN / 2)] = make_float2(acc0, acc1);
    }
}

// ---------------------------------------------------------------------------
// Kernel B (v4): the sequential scan, 128 threads/CTA, 4 n per thread.
// One warp per SMSP -> half the issue + MIO pressure of the 256-thread
// version while the serial dependency chain is unchanged.
// hid[b,t,:] holds Inp on entry (consumed, then overwritten). Inp prefetched
// 2 steps ahead (alias-safe: slot s+2 written only at iteration s+2).
// ---------------------------------------------------------------------------
__global__ __launch_bounds__(128, 1) void scan_kernel(const float* __restrict__ Vw,
                                                      const float* __restrict__ Uw,
                                                      const float* __restrict__ h0,
                                                      float* hid) {
    const int b    = blockIdx.x;
    const int tid  = threadIdx.x;
    const int lane = tid & 31;
    const int warp = tid >> 5;          // 0..3
    const int n0   = tid * 4;

    __shared__ u64 s_wsum[2][4][8];     // [buf][warp][packed low pair]
    __shared__ u64 s_low[4][8];         // [warp][packed low pair]

    // V packed over r-pairs: Vp[k][j] = (Vw[2j][n0+k], Vw[2j+1][n0+k])
    u64 Vp[4][8];
#pragma unroll
    for (int j = 0; j < 8; j++)
#pragma unroll
        for (int k = 0; k < 4; k++)
            Vp[k][j] = pk2(Vw[(2 * j) * NN + n0 + k], Vw[(2 * j + 1) * NN + n0 + k]);

    // U rows contiguous in r: Up[k][j] = (Uw[n0+k][2j], Uw[n0+k][2j+1])
    u64 Up[4][8];
#pragma unroll
    for (int k = 0; k < 4; k++) {
        const u64* up = reinterpret_cast<const u64*>(Uw + (size_t)(n0 + k) * RR);
#pragma unroll
        for (int j = 0; j < 8; j++) Up[k][j] = up[j];
    }

    float h[4];
#pragma unroll
    for (int k = 0; k < 4; k++) h[k] = h0[n0 + k];

    // hid viewed as float4, one slot per thread per step (coalesced STG.128)
    float4* hp = reinterpret_cast<float4*>(hid) + (size_t)b * TT * (NN / 4) + tid;
    const size_t STRD = NN / 4;

    float4 iv_a = __ldg(&hp[0]);
    float4 iv_b = __ldg(&hp[STRD]);

    const unsigned FULL = 0xFFFFFFFFu;

    for (int s = 0; s < TT; s++) {
        const int sp = (s + 2 < TT) ? (s + 2) : (TT - 1);
        float4 iv_c = __ldg(&hp[(size_t)sp * STRD]);

        float ph0 = fast_tanh(h[0]);
        float ph1 = fast_tanh(h[1]);
        float ph2 = fast_tanh(h[2]);
        float ph3 = fast_tanh(h[3]);
        u64 PH0 = pk2(ph0, ph0);
        u64 PH1 = pk2(ph1, ph1);
        u64 PH2 = pk2(ph2, ph2);
        u64 PH3 = pk2(ph3, ph3);

        // partials: P[j] = (low[2j],low[2j+1]) contribution of my 4 n
        u64 P[8];
#pragma unroll
        for (int j = 0; j < 8; j++) {
            u64 e = fma2(PH1, Vp[1][j], mul2(PH0, Vp[0][j]));
            u64 o = fma2(PH3, Vp[3][j], mul2(PH2, Vp[2][j]));
            P[j] = add2(e, o);
        }

        // in-warp packed fold over lane bits 16,8,4 (j 8->1), tails bits 2,1.
        // Survivor at lane L: packed pair a=(L>>2)&7 summed over all 32 lanes.
#pragma unroll
        for (int j = 0; j < 4; j++) {
            bool hi = (lane & 16) != 0;
            u64 keep = hi ? P[j + 4] : P[j];
            u64 send = hi ? P[j] : P[j + 4];
            P[j] = add2(keep, __shfl_xor_sync(FULL, send, 16));
        }
#pragma unroll
        for (int j = 0; j < 2; j++) {
            bool hi = (lane & 8) != 0;
            u64 keep = hi ? P[j + 2] : P[j];
            u64 send = hi ? P[j] : P[j + 2];
            P[j] = add2(keep, __shfl_xor_sync(FULL, send, 8));
        }
        {
            bool hi = (lane & 4) != 0;
            u64 keep = hi ? P[1] : P[0];
            u64 send = hi ? P[0] : P[1];
            P[0] = add2(keep, __shfl_xor_sync(FULL, send, 4));
        }
        P[0] = add2(P[0], __shfl_xor_sync(FULL, P[0], 2));
        P[0] = add2(P[0], __shfl_xor_sync(FULL, P[0], 1));

        const int buf = s & 1;
        if ((lane & 3) == 0) s_wsum[buf][warp][(lane >> 2) & 7] = P[0];
        __syncthreads();

        // cross-warp combine: lanes 0..7 sum the 4 warp values for pair a=lane
        if (lane < 8) {
            u64 a01 = add2(s_wsum[buf][0][lane], s_wsum[buf][1][lane]);
            u64 a23 = add2(s_wsum[buf][2][lane], s_wsum[buf][3][lane]);
            s_low[warp][lane] = add2(a01, a23);
        }
        __syncwarp();

        // broadcast low[16] back as 4x LDS.128 (per-warp slot, conflict-free)
        u64 LOW[8];
        {
            const ulonglong2* lp = reinterpret_cast<const ulonglong2*>(s_low[warp]);
#pragma unroll
            for (int q = 0; q < 4; q++) {
                ulonglong2 t = lp[q];
                LOW[2 * q]     = t.x;
                LOW[2 * q + 1] = t.y;
            }
        }

        // rec[k] = dot(low, U[n0+k]) , packed over r-pairs, 2 chains per n
        float rec[4];
#pragma unroll
        for (int k = 0; k < 4; k++) {
            u64 c0 = mul2(LOW[0], Up[k][0]);
            u64 c1 = mul2(LOW[1], Up[k][1]);
#pragma unroll
            for (int j = 2; j < 8; j += 2) {
                c0 = fma2(LOW[j],     Up[k][j],     c0);
                c1 = fma2(LOW[j + 1], Up[k][j + 1], c1);
            }
            float lo, hi2;
            upk2(add2(c0, c1), lo, hi2);
            rec[k] = lo + hi2;
        }

        h[0] = fmaf(1.0f - AA, h[0], AA * (rec[0] + iv_a.x));
        h[1] = fmaf(1.0f - AA, h[1], AA * (rec[1] + iv_a.y));
        h[2] = fmaf(1.0f - AA, h[2], AA * (rec[2] + iv_a.z));
        h[3] = fmaf(1.0f - AA, h[3], AA * (rec[3] + iv_a.w));

        hp[(size_t)s * STRD] = make_float4(h[0], h[1], h[2], h[3]);

        iv_a = iv_b;
        iv_b = iv_c;
    }
}

// ---------------------------------------------------------------------------
// Kernel C: out[b,t,o] = sum_n tanh(hidden[b,t,n]) * Out_w[o,n]
// warp per (b,t) row; Out_w staged in smem; coalesced float4 hidden reads.
// ---------------------------------------------------------------------------
__global__ __launch_bounds__(256) void out_kernel(const float* __restrict__ hid,
                                                  const float* __restrict__ Ow,
                                                  float* __restrict__ outp) {
    __shared__ float4 s_w[OUTC * NN / 4];  // 16 KB
    const int tid  = threadIdx.x;
    const int lane = tid & 31;
    const int warp = tid >> 5;

    const float4* ow4 = reinterpret_cast<const float4*>(Ow);
    for (int i = tid; i < OUTC * NN / 4; i += 256) s_w[i] = ow4[i];
    __syncthreads();

    const size_t row = (size_t)blockIdx.x * 8 + warp;  // < B*T
    const float4* h4 = reinterpret_cast<const float4*>(hid) + row * (NN / 4);

    float acc[OUTC];
#pragma unroll
    for (int o = 0; o < OUTC; o++) acc[o] = 0.0f;

#pragma unroll
    for (int i = 0; i < 4; i++) {
        float4 hv = __ldg(&h4[i * 32 + lane]);
        float t0 = fast_tanh(hv.x);
        float t1 = fast_tanh(hv.y);
        float t2 = fast_tanh(hv.z);
        float t3 = fast_tanh(hv.w);
#pragma unroll
        for (int o = 0; o < OUTC; o++) {
            float4 wv = s_w[o * (NN / 4) + i * 32 + lane];
            acc[o] = fmaf(t0, wv.x, fmaf(t1, wv.y, fmaf(t2, wv.z, fmaf(t3, wv.w, acc[o]))));
        }
    }

    const unsigned FULL = 0xFFFFFFFFu;
#pragma unroll
    for (int j = 0; j < 4; j++) {
        bool hi = (lane & 16) != 0;
        float keep = hi ? acc[j + 4] : acc[j];
        float send = hi ? acc[j] : acc[j + 4];
        acc[j] = keep + __shfl_xor_sync(FULL, send, 16);
    }
#pragma unroll
    for (int j = 0; j < 2; j++) {
        bool hi = (lane & 8) != 0;
        float keep = hi ? acc[j + 2] : acc[j];
        float send = hi ? acc[j] : acc[j + 2];
        acc[j] = keep + __shfl_xor_sync(FULL, send, 8);
    }
    {
        bool hi = (lane & 4) != 0;
        float keep = hi ? acc[1] : acc[0];
        float send = hi ? acc[0] : acc[1];
        acc[0] = keep + __shfl_xor_sync(FULL, send, 4);
    }
    acc[0] += __shfl_xor_sync(FULL, acc[0], 2);
    acc[0] += __shfl_xor_sync(FULL, acc[0], 1);

    if ((lane & 3) == 0)
        outp[row * OUTC + ((lane >> 2) & 7)] = acc[0];
}

// ---------------------------------------------------------------------------
// kernel_launch: inputs per metadata order:
//   0 Batch_Input [B,T,INC], 1 In_w [N,INC], 2 V_w [R,N], 3 U_w [N,R],
//   4 Out_w [OUTC,N], 5 hidden_0 [N]
// d_out: hidden_t [B,T,N] followed by out [B,T,OUTC]  (float32)
// ---------------------------------------------------------------------------
extern "C" void kernel_launch(void* const* d_in, const int* in_sizes, int n_in,
                              void* d_out, int out_size) {
    const float* x   = (const float*)d_in[0];
    const float* inw = (const float*)d_in[1];
    const float* vw  = (const float*)d_in[2];
    const float* uw  = (const float*)d_in[3];
    const float* ow  = (const float*)d_in[4];
    const float* h0  = (const float*)d_in[5];

    float* hid  = (float*)d_out;
    float* outp = hid + (size_t)BB * TT * NN;

    inp_kernel<<<BB * TT / IROWS, 256>>>(x, inw, hid);  // Inp staged into hid
    scan_kernel<<<BB, 128>>>(vw, uw, h0, hid);          // reads Inp, writes h
    out_kernel<<<BB * TT / 8, 256>>>(hid, ow, outp);
}

// round 10
// speedup vs baseline: 1.0345x; 1.0345x over previous
#include <cuda_runtime.h>
#include <cstdint>

// Problem constants (fixed by the reference setup)
#define BB   64
#define TT   1024
#define INC  16
#define NN   512
#define RR   16
#define OUTC 8
#define AA   0.1f   // DT / TAU

typedef unsigned long long u64;

// ---------------- packed f32x2 helpers (sm_103a dual-fp32 pipe) --------------
__device__ __forceinline__ u64 pk2(float lo, float hi) {
    u64 r; asm("mov.b64 %0, {%1, %2};" : "=l"(r) : "f"(lo), "f"(hi)); return r;
}
__device__ __forceinline__ void upk2(u64 v, float& lo, float& hi) {
    asm("mov.b64 {%0, %1}, %2;" : "=f"(lo), "=f"(hi) : "l"(v));
}
__device__ __forceinline__ u64 fma2(u64 a, u64 b, u64 c) {
    u64 d; asm("fma.rn.f32x2 %0, %1, %2, %3;" : "=l"(d) : "l"(a), "l"(b), "l"(c)); return d;
}
__device__ __forceinline__ u64 mul2(u64 a, u64 b) {
    u64 d; asm("mul.rn.f32x2 %0, %1, %2;" : "=l"(d) : "l"(a), "l"(b)); return d;
}
__device__ __forceinline__ u64 add2(u64 a, u64 b) {
    u64 d; asm("add.rn.f32x2 %0, %1, %2;" : "=l"(d) : "l"(a), "l"(b)); return d;
}

// Accurate-enough fast tanh: 1 - 2/(exp(2x)+1) via ex2.approx + rcp.approx.
__device__ __forceinline__ float fast_tanh(float x) {
    float e;
    asm("ex2.approx.f32 %0, %1;" : "=f"(e) : "f"(x * 2.885390082f)); // 2*log2(e)
    float r;
    asm("rcp.approx.f32 %0, %1;" : "=f"(r) : "f"(e + 1.0f));
    return fmaf(-2.0f, r, 1.0f);
}

// ---------------------------------------------------------------------------
// Kernel A: Inp[b,t,n] = sum_i X[b,t,i] * In_w[n,i], written into the hidden
// region of d_out (scratch aliasing with the scan). Tiled, In_w in registers.
// ---------------------------------------------------------------------------
#define IROWS 64
__global__ __launch_bounds__(256) void inp_kernel(const float* __restrict__ x,
                                                  const float* __restrict__ inw,
                                                  float* __restrict__ inp_out) {
    const int tid = threadIdx.x;
    const int r0  = blockIdx.x * IROWS;
    __shared__ float4 sx4[IROWS * INC / 4];

    sx4[tid] = reinterpret_cast<const float4*>(x)[(size_t)r0 * (INC / 4) + tid];

    const int n0 = tid * 2;
    float w0[INC], w1[INC];
    {
        const float4* a4 = reinterpret_cast<const float4*>(inw + (size_t)n0 * INC);
        const float4* b4 = reinterpret_cast<const float4*>(inw + (size_t)(n0 + 1) * INC);
#pragma unroll
        for (int i = 0; i < 4; i++) {
            float4 a = __ldg(&a4[i]);
            w0[4 * i + 0] = a.x; w0[4 * i + 1] = a.y; w0[4 * i + 2] = a.z; w0[4 * i + 3] = a.w;
            float4 c = __ldg(&b4[i]);
            w1[4 * i + 0] = c.x; w1[4 * i + 1] = c.y; w1[4 * i + 2] = c.z; w1[4 * i + 3] = c.w;
        }
    }
    __syncthreads();

    float2* out2 = reinterpret_cast<float2*>(inp_out) + (size_t)r0 * (NN / 2) + tid;

#pragma unroll 4
    for (int j = 0; j < IROWS; j++) {
        float acc0 = 0.0f, acc1 = 0.0f;
#pragma unroll
        for (int q = 0; q < 4; q++) {
            float4 xv = sx4[j * 4 + q];
            acc0 = fmaf(w0[4 * q + 0], xv.x, acc0);
            acc0 = fmaf(w0[4 * q + 1], xv.y, acc0);
            acc0 = fmaf(w0[4 * q + 2], xv.z, acc0);
            acc0 = fmaf(w0[4 * q + 3], xv.w, acc0);
            acc1 = fmaf(w1[4 * q + 0], xv.x, acc1);
            acc1 = fmaf(w1[4 * q + 1], xv.y, acc1);
            acc1 = fmaf(w1[4 * q + 2], xv.z, acc1);
            acc1 = fmaf(w1[4 * q + 3], xv.w, acc1);
        }
        out2[(size_t)j * (NN / 2)] = make_float2(acc0, acc1);
    }
}

// ---------------------------------------------------------------------------
// Kernel B (v5): sequential scan, 128 threads/CTA, 4 n per thread.
// Chain-latency optimized: NO divergent branches in the loop body (zero
// BSSY/BSYNC), only 3 SHFL fold levels (tail folds moved into the smem
// combine tree), broadcast of low[] via SHFL instead of a 2nd smem trip.
//
// Reduction scheme per step:
//   P[j] = packed partial of (low[2j],low[2j+1]) over my 4 n          (j<8)
//   3 sel-fold levels over lane bits 16,8,4:
//     lane L then holds P[0] = pair a=(L>>2)&7 summed over the 8 lanes
//     {L ^ span(4,8,16)}; sublane c = L&3 indexes 4 disjoint subsets.
//   ALL lanes store to s_wsum[buf][warp][c][a]  (distinct slots, unguarded)
//   __syncthreads
//   ALL lanes (a = lane&7, lanes 8..31 redundant): comb = sum over the 16
//     slots {warp w<4} x {sublane c<4}  (16 LDS.64 + balanced add tree)
//   LOW[a'] = __shfl_sync(comb, a')  for a'=0..7  (lanes 0..7 are sources)
//   rec = U @ low (packed), h update, STG.128; Inp prefetched 2 steps ahead.
// ---------------------------------------------------------------------------
__global__ __launch_bounds__(128, 1) void scan_kernel(const float* __restrict__ Vw,
                                                      const float* __restrict__ Uw,
                                                      const float* __restrict__ h0,
                                                      float* hid) {
    const int b    = blockIdx.x;
    const int tid  = threadIdx.x;
    const int lane = tid & 31;
    const int warp = tid >> 5;          // 0..3
    const int n0   = tid * 4;

    __shared__ u64 s_wsum[2][4][4][8];  // [buf][warp][sublane c][pair a]

    // V packed over r-pairs: Vp[k][j] = (Vw[2j][n0+k], Vw[2j+1][n0+k])
    u64 Vp[4][8];
#pragma unroll
    for (int j = 0; j < 8; j++)
#pragma unroll
        for (int k = 0; k < 4; k++)
            Vp[k][j] = pk2(Vw[(2 * j) * NN + n0 + k], Vw[(2 * j + 1) * NN + n0 + k]);

    // U rows contiguous in r: Up[k][j] = (Uw[n0+k][2j], Uw[n0+k][2j+1])
    u64 Up[4][8];
#pragma unroll
    for (int k = 0; k < 4; k++) {
        const u64* up = reinterpret_cast<const u64*>(Uw + (size_t)(n0 + k) * RR);
#pragma unroll
        for (int j = 0; j < 8; j++) Up[k][j] = up[j];
    }

    float h[4];
#pragma unroll
    for (int k = 0; k < 4; k++) h[k] = h0[n0 + k];

    // hid viewed as float4, one slot per thread per step (coalesced STG.128)
    float4* hp = reinterpret_cast<float4*>(hid) + (size_t)b * TT * (NN / 4) + tid;
    const size_t STRD = NN / 4;

    float4 iv_a = __ldg(&hp[0]);
    float4 iv_b = __ldg(&hp[STRD]);

    const unsigned FULL = 0xFFFFFFFFu;
    const int a_mine = lane & 7;        // pair this lane combines (redundant >=8)
    const int c_mine = lane & 3;        // sublane id
    const int a_st   = (lane >> 2) & 7; // pair this lane's fold survivor holds

    for (int s = 0; s < TT; s++) {
        const int sp = (s + 2 < TT) ? (s + 2) : (TT - 1);
        float4 iv_c = __ldg(&hp[(size_t)sp * STRD]);

        float ph0 = fast_tanh(h[0]);
        float ph1 = fast_tanh(h[1]);
        float ph2 = fast_tanh(h[2]);
        float ph3 = fast_tanh(h[3]);
        u64 PH0 = pk2(ph0, ph0);
        u64 PH1 = pk2(ph1, ph1);
        u64 PH2 = pk2(ph2, ph2);
        u64 PH3 = pk2(ph3, ph3);

        // partials: P[j] = (low[2j],low[2j+1]) contribution of my 4 n
        u64 P[8];
#pragma unroll
        for (int j = 0; j < 8; j++) {
            u64 e = fma2(PH1, Vp[1][j], mul2(PH0, Vp[0][j]));
            u64 o = fma2(PH3, Vp[3][j], mul2(PH2, Vp[2][j]));
            P[j] = add2(e, o);
        }

        // 3 sel-fold levels (bits 16, 8, 4): 8 pairs -> 1 pair per lane
#pragma unroll
        for (int j = 0; j < 4; j++) {
            bool hi = (lane & 16) != 0;
            u64 keep = hi ? P[j + 4] : P[j];
            u64 send = hi ? P[j] : P[j + 4];
            P[j] = add2(keep, __shfl_xor_sync(FULL, send, 16));
        }
#pragma unroll
        for (int j = 0; j < 2; j++) {
            bool hi = (lane & 8) != 0;
            u64 keep = hi ? P[j + 2] : P[j];
            u64 send = hi ? P[j] : P[j + 2];
            P[j] = add2(keep, __shfl_xor_sync(FULL, send, 8));
        }
        {
            bool hi = (lane & 4) != 0;
            u64 keep = hi ? P[1] : P[0];
            u64 send = hi ? P[0] : P[1];
            P[0] = add2(keep, __shfl_xor_sync(FULL, send, 4));
        }

        // every lane stores its distinct (c, a) partial — no guard, no BSSY
        const int buf = s & 1;
        s_wsum[buf][warp][c_mine][a_st] = P[0];
        __syncthreads();

        // every lane redundantly combines pair a_mine over 4 warps x 4 sublanes
        // (16 LDS.64, latency-balanced tree) — no guard, no BSSY
        u64 t0, t1;
        {
            u64 x0 = add2(add2(s_wsum[buf][0][0][a_mine], s_wsum[buf][0][1][a_mine]),
                          add2(s_wsum[buf][0][2][a_mine], s_wsum[buf][0][3][a_mine]));
            u64 x1 = add2(add2(s_wsum[buf][1][0][a_mine], s_wsum[buf][1][1][a_mine]),
                          add2(s_wsum[buf][1][2][a_mine], s_wsum[buf][1][3][a_mine]));
            u64 x2 = add2(add2(s_wsum[buf][2][0][a_mine], s_wsum[buf][2][1][a_mine]),
                          add2(s_wsum[buf][2][2][a_mine], s_wsum[buf][2][3][a_mine]));
            u64 x3 = add2(add2(s_wsum[buf][3][0][a_mine], s_wsum[buf][3][1][a_mine]),
                          add2(s_wsum[buf][3][2][a_mine], s_wsum[buf][3][3][a_mine]));
            t0 = add2(x0, x1);
            t1 = add2(x2, x3);
        }
        u64 comb = add2(t0, t1);   // lanes 0..7 hold pairs 0..7 (rest redundant)

        // broadcast low[16] to all lanes: 8 packed SHFLs from lanes 0..7
        u64 LOW[8];
#pragma unroll
        for (int a = 0; a < 8; a++) LOW[a] = __shfl_sync(FULL, comb, a);

        // rec[k] = dot(low, U[n0+k]), packed over r-pairs, 2 chains per n
        float rec[4];
#pragma unroll
        for (int k = 0; k < 4; k++) {
            u64 c0 = mul2(LOW[0], Up[k][0]);
            u64 c1 = mul2(LOW[1], Up[k][1]);
#pragma unroll
            for (int j = 2; j < 8; j += 2) {
                c0 = fma2(LOW[j],     Up[k][j],     c0);
                c1 = fma2(LOW[j + 1], Up[k][j + 1], c1);
            }
            float lo, hi2;
            upk2(add2(c0, c1), lo, hi2);
            rec[k] = lo + hi2;
        }

        h[0] = fmaf(1.0f - AA, h[0], AA * (rec[0] + iv_a.x));
        h[1] = fmaf(1.0f - AA, h[1], AA * (rec[1] + iv_a.y));
        h[2] = fmaf(1.0f - AA, h[2], AA * (rec[2] + iv_a.z));
        h[3] = fmaf(1.0f - AA, h[3], AA * (rec[3] + iv_a.w));

        hp[(size_t)s * STRD] = make_float4(h[0], h[1], h[2], h[3]);

        iv_a = iv_b;
        iv_b = iv_c;
    }
}

// ---------------------------------------------------------------------------
// Kernel C: out[b,t,o] = sum_n tanh(hidden[b,t,n]) * Out_w[o,n]
// warp per (b,t) row; Out_w staged in smem; coalesced float4 hidden reads.
// ---------------------------------------------------------------------------
__global__ __launch_bounds__(256) void out_kernel(const float* __restrict__ hid,
                                                  const float* __restrict__ Ow,
                                                  float* __restrict__ outp) {
    __shared__ float4 s_w[OUTC * NN / 4];  // 16 KB
    const int tid  = threadIdx.x;
    const int lane = tid & 31;
    const int warp = tid >> 5;

    const float4* ow4 = reinterpret_cast<const float4*>(Ow);
    for (int i = tid; i < OUTC * NN / 4; i += 256) s_w[i] = ow4[i];
    __syncthreads();

    const size_t row = (size_t)blockIdx.x * 8 + warp;  // < B*T
    const float4* h4 = reinterpret_cast<const float4*>(hid) + row * (NN / 4);

    float acc[OUTC];
#pragma unroll
    for (int o = 0; o < OUTC; o++) acc[o] = 0.0f;

#pragma unroll
    for (int i = 0; i < 4; i++) {
        float4 hv = __ldg(&h4[i * 32 + lane]);
        float t0 = fast_tanh(hv.x);
        float t1 = fast_tanh(hv.y);
        float t2 = fast_tanh(hv.z);
        float t3 = fast_tanh(hv.w);
#pragma unroll
        for (int o = 0; o < OUTC; o++) {
            float4 wv = s_w[o * (NN / 4) + i * 32 + lane];
            acc[o] = fmaf(t0, wv.x, fmaf(t1, wv.y, fmaf(t2, wv.z, fmaf(t3, wv.w, acc[o]))));
        }
    }

    const unsigned FULL = 0xFFFFFFFFu;
#pragma unroll
    for (int j = 0; j < 4; j++) {
        bool hi = (lane & 16) != 0;
        float keep = hi ? acc[j + 4] : acc[j];
        float send = hi ? acc[j] : acc[j + 4];
        acc[j] = keep + __shfl_xor_sync(FULL, send, 16);
    }
#pragma unroll
    for (int j = 0; j < 2; j++) {
        bool hi = (lane & 8) != 0;
        float keep = hi ? acc[j + 2] : acc[j];
        float send = hi ? acc[j] : acc[j + 2];
        acc[j] = keep + __shfl_xor_sync(FULL, send, 8);
    }
    {
        bool hi = (lane & 4) != 0;
        float keep = hi ? acc[1] : acc[0];
        float send = hi ? acc[0] : acc[1];
        acc[0] = keep + __shfl_xor_sync(FULL, send, 4);
    }
    acc[0] += __shfl_xor_sync(FULL, acc[0], 2);
    acc[0] += __shfl_xor_sync(FULL, acc[0], 1);

    if ((lane & 3) == 0)
        outp[row * OUTC + ((lane >> 2) & 7)] = acc[0];
}

// ---------------------------------------------------------------------------
// kernel_launch: inputs per metadata order:
//   0 Batch_Input [B,T,INC], 1 In_w [N,INC], 2 V_w [R,N], 3 U_w [N,R],
//   4 Out_w [OUTC,N], 5 hidden_0 [N]
// d_out: hidden_t [B,T,N] followed by out [B,T,OUTC]  (float32)
// ---------------------------------------------------------------------------
extern "C" void kernel_launch(void* const* d_in, const int* in_sizes, int n_in,
                              void* d_out, int out_size) {
    const float* x   = (const float*)d_in[0];
    const float* inw = (const float*)d_in[1];
    const float* vw  = (const float*)d_in[2];
    const float* uw  = (const float*)d_in[3];
    const float* ow  = (const float*)d_in[4];
    const float* h0  = (const float*)d_in[5];

    float* hid  = (float*)d_out;
    float* outp = hid + (size_t)BB * TT * NN;

    inp_kernel<<<BB * TT / IROWS, 256>>>(x, inw, hid);  // Inp staged into hid
    scan_kernel<<<BB, 128>>>(vw, uw, h0, hid);          // reads Inp, writes h
    out_kernel<<<BB * TT / 8, 256>>>(hid, ow, outp);
}